// round 13
// baseline (speedup 1.0000x reference)
#include <cuda_runtime.h>

#define B_SZ    16384
#define NL      131072
#define THREADS 256
#define NBLOCKS 512                    // 512*256 = 131072 threads = NL
#define NTHREADS (NBLOCKS * THREADS)   // 131072
#define NCLS    20
// cells: 6 per thread + 1 extra for tid < 16384  (6*131072 + 16384 = 802816)
// hot region: cells [0, 4*NTHREADS) = 524288 cells = 60 MB (evict_last)
#define HOT_CELLS  (4u * NTHREADS)
#define HOT_FLOATS ((size_t)HOT_CELLS * 30u)

__device__ double       g_acc   = 0.0;
__device__ unsigned int g_count = 0;

__device__ __forceinline__ unsigned long long pol_last() {
    unsigned long long p;
    asm volatile("createpolicy.fractional.L2::evict_last.b64 %0, 1.0;" : "=l"(p));
    return p;
}
__device__ __forceinline__ unsigned long long pol_first() {
    unsigned long long p;
    asm volatile("createpolicy.fractional.L2::evict_first.b64 %0, 1.0;" : "=l"(p));
    return p;
}
__device__ __forceinline__ float2 ldg_pol(const float2* __restrict__ p,
                                          unsigned long long pol) {
    float2 v;
    asm volatile("ld.global.nc.L2::cache_hint.v2.f32 {%0,%1}, [%2], %3;"
                 : "=f"(v.x), "=f"(v.y) : "l"(p), "l"(pol));
    return v;
}

__device__ __forceinline__ float iou_pair(float ax, float ay, float aw, float ah,
                                          float gx, float gy, float gw, float gh) {
    float ax1 = ax - aw * 0.5f, ax2 = ax + aw * 0.5f;
    float ay1 = ay - ah * 0.5f, ay2 = ay + ah * 0.5f;
    float gx1 = gx - gw * 0.5f, gx2 = gx + gw * 0.5f;
    float gy1 = gy - gh * 0.5f, gy2 = gy + gh * 0.5f;
    float iw = fmaxf(0.0f, fminf(ax2, gx2) - fmaxf(ax1, gx1));
    float ih = fmaxf(0.0f, fminf(ay2, gy2) - fmaxf(ay1, gy1));
    float inter = iw * ih;
    float uni = aw * ah + gw * gh - inter;
    return inter / (uni + 1e-6f);
}

__global__ void __launch_bounds__(THREADS)
yolo_loss_kernel(const float* __restrict__ out, const float* __restrict__ labels,
                 float* __restrict__ result) {
    unsigned tid = blockIdx.x * THREADS + threadIdx.x;   // < 131072
    const unsigned long long pL = pol_last();
    const unsigned long long pF = pol_first();

    // ---------- label header (hot: tiny, keep resident) ----------
    const float2* Lp = reinterpret_cast<const float2*>(labels + (size_t)tid * 6);
    float2 l0 = ldg_pol(Lp + 0, pL);   // b, cls
    float2 l1 = ldg_pol(Lp + 1, pL);   // gx, gy
    float2 l2 = ldg_pol(Lp + 2, pL);   // gw, gh

    // ---------- cell (no-object) loads: k<4 hot / k>=4 cold ----------
    float2 cv[6];
    #pragma unroll
    for (int k = 0; k < 6; k++) {
        unsigned cell = tid + k * NTHREADS;
        const float2* cp = reinterpret_cast<const float2*>(out + (size_t)cell * 30 + 20);
        cv[k] = ldg_pol(cp, (k < 4) ? pL : pF);
    }
    bool extra = tid < 16384u;
    float2 ce = make_float2(0.0f, 0.0f);
    if (extra) {
        unsigned cell = 6u * NTHREADS + tid;
        ce = ldg_pol(reinterpret_cast<const float2*>(out + (size_t)cell * 30 + 20), pF);
    }

    // ---------- label cell gather (depends on header) ----------
    int b = (int)l0.x;
    int c = (int)l0.y;
    float gx = l1.x, gy = l1.y, gw = l2.x, gh = l2.y;

    float rowf = floorf(gx * 7.0f);
    float colf = floorf(gy * 7.0f);
    int row = (int)rowf, col = (int)colf;

    size_t base = ((size_t)b * 49 + (size_t)(row * 7 + col)) * 30;
    const float2* p2 = reinterpret_cast<const float2*>(out + base);
    const unsigned long long pG = (base < HOT_FLOATS) ? pL : pF;

    // Batch A: channels 0..15
    float2 va[8];
    #pragma unroll
    for (int k = 0; k < 8; k++) va[k] = ldg_pol(p2 + k, pG);

    // ---- consume cell loads while gather is in flight ----
    float noobj = 0.0f;
    #pragma unroll
    for (int k = 0; k < 6; k++)
        noobj += cv[k].x * cv[k].x + cv[k].y * cv[k].y;
    if (extra) noobj += ce.x * ce.x + ce.y * ce.y;
    noobj *= 0.5f;

    float sumsq = 0.0f;
    float pvc = 0.0f;
    #pragma unroll
    for (int k = 0; k < 8; k++) {
        sumsq += va[k].x * va[k].x + va[k].y * va[k].y;
        if (c == 2 * k)     pvc = va[k].x;
        if (c == 2 * k + 1) pvc = va[k].y;
    }

    // Batch B: channels 16..29
    float2 vb[7];
    #pragma unroll
    for (int k = 0; k < 7; k++) vb[k] = ldg_pol(p2 + 8 + k, pG);

    sumsq += vb[0].x * vb[0].x + vb[0].y * vb[0].y
           + vb[1].x * vb[1].x + vb[1].y * vb[1].y;
    if (c == 16) pvc = vb[0].x;
    if (c == 17) pvc = vb[0].y;
    if (c == 18) pvc = vb[1].x;
    if (c == 19) pvc = vb[1].y;
    float cls = sumsq - 2.0f * pvc + 1.0f;

    // channels: 20=vb[2].x 21=vb[2].y 22=vb[3].x 23=vb[3].y 24=vb[4].x
    //           25=vb[4].y 26=vb[5].x 27=vb[5].y 28=vb[6].x 29=vb[6].y
    const float inv_s = 1.0f / 7.0f;
    float iou1 = iou_pair((rowf + vb[3].x) * inv_s, (colf + vb[3].y) * inv_s,
                          vb[4].x, vb[4].y, gx, gy, gw, gh);
    float iou2 = iou_pair((rowf + vb[5].x) * inv_s, (colf + vb[5].y) * inv_s,
                          vb[6].x, vb[6].y, gx, gy, gw, gh);
    bool use1 = (iou1 >= iou2);

    float gcx = gx * 7.0f - rowf;
    float gcy = gy * 7.0f - colf;

    float px = use1 ? vb[3].x : vb[5].x;
    float py = use1 ? vb[3].y : vb[5].y;
    float pw = use1 ? vb[4].x : vb[6].x;
    float ph = use1 ? vb[4].y : vb[6].y;

    const float eps = 1e-6f;
    float dx = px - gcx;
    float dy = py - gcy;
    float dw = sqrtf(pw + eps) - sqrtf(gw + eps);
    float dh = sqrtf(ph + eps) - sqrtf(gh + eps);
    float coor = 5.0f * (dx * dx + dy * dy + dw * dw + dh * dh);

    float cp = use1 ? vb[2].x : vb[2].y;
    float ct = use1 ? iou1 : iou2;
    float cd = cp - ct;
    float conf = cd * cd - 0.5f * cp * cp;

    float local = noobj + cls + coor + conf;

    // block reduction: warp shuffles + shared
    #pragma unroll
    for (int o = 16; o > 0; o >>= 1)
        local += __shfl_down_sync(0xffffffffu, local, o);

    __shared__ float wsum[THREADS / 32];
    int lane = threadIdx.x & 31;
    int wid = threadIdx.x >> 5;
    if (lane == 0) wsum[wid] = local;
    __syncthreads();

    if (wid == 0) {
        float v = (lane < THREADS / 32) ? wsum[lane] : 0.0f;
        #pragma unroll
        for (int o = 4; o > 0; o >>= 1)
            v += __shfl_down_sync(0xffffffffu, v, o);
        if (lane == 0) {
            atomicAdd(&g_acc, (double)v);
            __threadfence();
            unsigned t = atomicAdd(&g_count, 1u);
            if (t == (unsigned)(gridDim.x - 1)) {
                // last block: publish result and reset state for next replay
                result[0] = (float)(g_acc / (double)B_SZ);
                g_acc = 0.0;
                g_count = 0u;
            }
        }
    }
}

extern "C" void kernel_launch(void* const* d_in, const int* in_sizes, int n_in,
                              void* d_out, int out_size) {
    const float* output = (const float*)d_in[0];
    const float* labels = (const float*)d_in[1];
    float* out = (float*)d_out;

    yolo_loss_kernel<<<NBLOCKS, THREADS>>>(output, labels, out);
}

// round 14
// speedup vs baseline: 1.4310x; 1.4310x over previous
#include <cuda_runtime.h>

#define B_SZ    16384
#define NL      131072
#define THREADS 256
#define NBLOCKS 512                    // 512*256 = 131072 threads = NL
#define NTHREADS (NBLOCKS * THREADS)   // 131072
#define NCLS    20
// cells: 6 per thread + 1 extra for tid < 16384  (6*131072 + 16384 = 802816)

__device__ double       g_acc   = 0.0;
__device__ unsigned int g_count = 0;

__device__ __forceinline__ float iou_pair(float ax, float ay, float aw, float ah,
                                          float gx, float gy, float gw, float gh) {
    float ax1 = ax - aw * 0.5f, ax2 = ax + aw * 0.5f;
    float ay1 = ay - ah * 0.5f, ay2 = ay + ah * 0.5f;
    float gx1 = gx - gw * 0.5f, gx2 = gx + gw * 0.5f;
    float gy1 = gy - gh * 0.5f, gy2 = gy + gh * 0.5f;
    float iw = fmaxf(0.0f, fminf(ax2, gx2) - fmaxf(ax1, gx1));
    float ih = fmaxf(0.0f, fminf(ay2, gy2) - fmaxf(ay1, gy1));
    float inter = iw * ih;
    float uni = aw * ah + gw * gh - inter;
    return inter / (uni + 1e-6f);
}

__global__ void __launch_bounds__(THREADS)
yolo_loss_kernel(const float* __restrict__ out, const float* __restrict__ labels,
                 float* __restrict__ result) {
    unsigned tid = blockIdx.x * THREADS + threadIdx.x;   // < 131072

    // ---------- label header ----------
    const float2* Lp = reinterpret_cast<const float2*>(labels + (size_t)tid * 6);
    float2 l0 = __ldg(Lp + 0);   // b, cls
    float2 l1 = __ldg(Lp + 1);   // gx, gy
    float2 l2 = __ldg(Lp + 2);   // gw, gh

    // ---------- cell (no-object) loads: 6(+1) strided float2 ----------
    float2 cv[6];
    #pragma unroll
    for (int k = 0; k < 6; k++) {
        unsigned cell = tid + k * NTHREADS;
        cv[k] = *reinterpret_cast<const float2*>(out + (size_t)cell * 30 + 20);
    }
    bool extra = tid < 16384u;
    float2 ce = make_float2(0.0f, 0.0f);
    if (extra) {
        unsigned cell = 6u * NTHREADS + tid;
        ce = *reinterpret_cast<const float2*>(out + (size_t)cell * 30 + 20);
    }

    // ---------- label cell gather: 8 x LDG.128 over aligned 128B window ----
    int b = (int)l0.x;
    int c = (int)l0.y;
    float gx = l1.x, gy = l1.y, gw = l2.x, gh = l2.y;

    float rowf = floorf(gx * 7.0f);
    float colf = floorf(gy * 7.0f);
    int row = (int)rowf, col = (int)colf;

    unsigned base  = ((unsigned)b * 49u + (unsigned)(row * 7 + col)) * 30u;
    unsigned abase = base & ~3u;              // 16B-aligned float index
    bool odd = (base & 2u) != 0u;             // cell starts +8B into window

    const float4* q = reinterpret_cast<const float4*>(out + abase);
    float4 w4[8];
    #pragma unroll
    for (int k = 0; k < 8; k++) w4[k] = __ldg(q + k);

    // ---- consume cell loads while gather is in flight ----
    float noobj = 0.0f;
    #pragma unroll
    for (int k = 0; k < 6; k++)
        noobj += cv[k].x * cv[k].x + cv[k].y * cv[k].y;
    if (extra) noobj += ce.x * ce.x + ce.y * ce.y;
    noobj *= 0.5f;

    float w[32];
    #pragma unroll
    for (int k = 0; k < 8; k++) {
        w[4 * k]     = w4[k].x;
        w[4 * k + 1] = w4[k].y;
        w[4 * k + 2] = w4[k].z;
        w[4 * k + 3] = w4[k].w;
    }
    // channel u[k] = w[k + 2*odd]

    // class loss = sum_{k<20} u[k]^2 - 2*u[c] + 1
    float s22 = 0.0f;
    #pragma unroll
    for (int k = 0; k < 22; k++) s22 += w[k] * w[k];
    // remove the two non-class extras inside w[0..21]
    float exA = odd ? w[0] : w[20];
    float exB = odd ? w[1] : w[21];
    float cls_sum = s22 - exA * exA - exB * exB;

    int c2 = c + (odd ? 2 : 0);              // u[c] = w[c2], c2 in 0..21
    float pvc = 0.0f;
    #pragma unroll
    for (int k = 0; k < 22; k++)
        if (c2 == k) pvc = w[k];
    float cls = cls_sum - 2.0f * pvc + 1.0f;

    // box/conf channels u[20..29] = w[20+2odd .. 29+2odd]
    float p20 = odd ? w[22] : w[20];
    float p21 = odd ? w[23] : w[21];
    float p22 = odd ? w[24] : w[22];
    float p23 = odd ? w[25] : w[23];
    float p24 = odd ? w[26] : w[24];
    float p25 = odd ? w[27] : w[25];
    float p26 = odd ? w[28] : w[26];
    float p27 = odd ? w[29] : w[27];
    float p28 = odd ? w[30] : w[28];
    float p29 = odd ? w[31] : w[29];

    const float inv_s = 1.0f / 7.0f;
    float iou1 = iou_pair((rowf + p22) * inv_s, (colf + p23) * inv_s,
                          p24, p25, gx, gy, gw, gh);
    float iou2 = iou_pair((rowf + p26) * inv_s, (colf + p27) * inv_s,
                          p28, p29, gx, gy, gw, gh);
    bool use1 = (iou1 >= iou2);

    float gcx = gx * 7.0f - rowf;
    float gcy = gy * 7.0f - colf;

    float px = use1 ? p22 : p26;
    float py = use1 ? p23 : p27;
    float pw = use1 ? p24 : p28;
    float ph = use1 ? p25 : p29;

    const float eps = 1e-6f;
    float dx = px - gcx;
    float dy = py - gcy;
    float dw = sqrtf(pw + eps) - sqrtf(gw + eps);
    float dh = sqrtf(ph + eps) - sqrtf(gh + eps);
    float coor = 5.0f * (dx * dx + dy * dy + dw * dw + dh * dh);

    float cp = use1 ? p20 : p21;
    float ct = use1 ? iou1 : iou2;
    float cd = cp - ct;
    float conf = cd * cd - 0.5f * cp * cp;

    float local = noobj + cls + coor + conf;

    // block reduction: warp shuffles + shared
    #pragma unroll
    for (int o = 16; o > 0; o >>= 1)
        local += __shfl_down_sync(0xffffffffu, local, o);

    __shared__ float wsum[THREADS / 32];
    int lane = threadIdx.x & 31;
    int wid = threadIdx.x >> 5;
    if (lane == 0) wsum[wid] = local;
    __syncthreads();

    if (wid == 0) {
        float v = (lane < THREADS / 32) ? wsum[lane] : 0.0f;
        #pragma unroll
        for (int o = 4; o > 0; o >>= 1)
            v += __shfl_down_sync(0xffffffffu, v, o);
        if (lane == 0) {
            atomicAdd(&g_acc, (double)v);
            __threadfence();
            unsigned t = atomicAdd(&g_count, 1u);
            if (t == (unsigned)(gridDim.x - 1)) {
                // last block: publish result and reset state for next replay
                result[0] = (float)(g_acc / (double)B_SZ);
                g_acc = 0.0;
                g_count = 0u;
            }
        }
    }
}

extern "C" void kernel_launch(void* const* d_in, const int* in_sizes, int n_in,
                              void* d_out, int out_size) {
    const float* output = (const float*)d_in[0];
    const float* labels = (const float*)d_in[1];
    float* out = (float*)d_out;

    yolo_loss_kernel<<<NBLOCKS, THREADS>>>(output, labels, out);
}